// round 15
// baseline (speedup 1.0000x reference)
#include <cuda_runtime.h>

// Problem constants (fixed for this instance)
#define HW_   262144          // H*W = 512*512
#define D_    32
#define C_    19
#define N_    2097152         // B*H*W
#define NGRP  65536           // N / 32
#define GRID_ 592
#define WPB   8
#define NWARP (GRID_ * WPB)   // 4736
#define PITCH 34              // bucket row pitch (floats)
#define EPS_  1e-8f

// ---------------- scratch (zero-initialized device globals) -----------------
// The in-kernel epilogue resets these, so every graph replay starts clean.
__device__ float    g_sumv[C_ * D_];   // per-class sums of x
__device__ float    g_sumn[C_ * D_];   // per-class sums of x/||x||
__device__ float    g_cnt[C_];         // per-class counts
__device__ unsigned g_done;            // finished-block counter

__global__ void __launch_bounds__(256, 3)
k_all(const float* __restrict__ in, const void* __restrict__ tgt,
      float* __restrict__ out) {
    __shared__ float bkt[WPB][32 * PITCH];   // per-warp private buckets
    __shared__ float rbuf[WPB][32];          // per-warp r values by slot
    __shared__ int   scnt[WPB][20];          // per-warp class histogram
    __shared__ float scntf[C_];              // block class counts
    __shared__ int   s_is64, s_last;

    const int t    = threadIdx.x;
    const int w    = t >> 5;
    const int lane = t & 31;
    const unsigned FULL = 0xffffffffu;

    if (t < C_) scntf[t] = 0.f;
    if (t == 0) {
        // int64 labels in [0,19): every odd 32-bit word is 0.
        const unsigned* wd = (const unsigned*)tgt;
        int is64 = 1;
        #pragma unroll
        for (int k = 0; k < 16; k++)
            if (wd[2 * k + 1] != 0u) is64 = 0;
        s_is64 = is64;
    }
    __syncthreads();
    const int is64 = s_is64;
    const long long* t64 = (const long long*)tgt;
    const int*       t32 = (const int*)tgt;

    float* const bw = bkt[w];
    float* const rw = rbuf[w];
    int*   const hw_ = scnt[w];

    // per-warp register accumulators: lane = dim, class = unrolled index
    float sv[C_], sn[C_];
    #pragma unroll
    for (int c = 0; c < C_; ++c) { sv[c] = 0.f; sn[c] = 0.f; }
    float cntacc = 0.f;                       // lane<19: count of class `lane`

    const int gw = blockIdx.x * WPB + w;
    for (int g = gw; g < NGRP; g += NWARP) {
        const int p0 = g << 5;
        const int p  = p0 + lane;
        const int b  = p0 >> 18;
        const int hw = (p0 & (HW_ - 1)) + lane;
        const float* bp = in + (size_t)b * ((size_t)D_ * HW_) + hw;
        int lab = is64 ? (int)t64[p] : t32[p];

        // -- warp-private counting sort: histogram + rank --
        if (lane < C_) hw_[lane] = 0;
        __syncwarp();
        unsigned m = __match_any_sync(FULL, lab);
        int lead   = __ffs(m) - 1;
        int rank   = __popc(m & ((1u << lane) - 1u));
        if (lane == lead) hw_[lab] = __popc(m);
        __syncwarp();
        int cv = (lane < C_) ? hw_[lane] : 0;
        int sc = cv;
        #pragma unroll
        for (int o = 1; o < 32; o <<= 1) {
            int nn = __shfl_up_sync(FULL, sc, o);
            if (lane >= o) sc += nn;
        }
        const int base = sc - cv;                       // exclusive scan
        const int slot = __shfl_sync(FULL, base, lab) + rank;
        if (lane < C_) cntacc += (float)cv;

        // -- load 32 dims (two MLP=16 batches) and scatter to bucket --
        float* row = &bw[slot * PITCH];
        float ss = 0.f;
        #pragma unroll
        for (int h = 0; h < 2; ++h) {
            float a[16];
            #pragma unroll
            for (int d = 0; d < 16; ++d)
                a[d] = bp[(size_t)(h * 16 + d) * HW_];
            #pragma unroll
            for (int d = 0; d < 16; ++d)
                ss = fmaf(a[d], a[d], ss);
            float2* r2 = (float2*)(row + h * 16);
            #pragma unroll
            for (int k = 0; k < 8; ++k)
                r2[k] = make_float2(a[2 * k], a[2 * k + 1]);
        }
        rw[slot] = rsqrtf(fmaxf(ss, 1e-24f));
        __syncwarp();

        // -- gather: class-contiguous slots into register accumulators --
        const float rr = rw[lane];                      // r of slot `lane`
        #pragma unroll
        for (int c = 0; c < C_; ++c) {
            const int cc = __shfl_sync(FULL, cv, c);
            const int bs = __shfl_sync(FULL, base, c);
            for (int k = 0; k < cc; ++k) {
                float a  = bw[(bs + k) * PITCH + lane]; // conflict-free
                float rk = __shfl_sync(FULL, rr, bs + k);
                sv[c] += a;
                sn[c] = fmaf(a, rk, sn[c]);
            }
        }
        __syncwarp();                                   // bucket reuse
    }

    // ---- block reduction: stage per-warp sums through smem (2 passes) ----
    __syncthreads();
    #pragma unroll
    for (int c = 0; c < C_; ++c) bw[c * 32 + lane] = sv[c];
    if (lane < C_) atomicAdd(&scntf[lane], cntacc);
    __syncthreads();
    for (int i = t; i < C_ * D_; i += 256) {
        float s = 0.f;
        #pragma unroll
        for (int w2 = 0; w2 < WPB; ++w2) s += bkt[w2][i];
        atomicAdd(&g_sumv[i], s);
    }
    __syncthreads();
    #pragma unroll
    for (int c = 0; c < C_; ++c) bw[c * 32 + lane] = sn[c];
    __syncthreads();
    for (int i = t; i < C_ * D_; i += 256) {
        float s = 0.f;
        #pragma unroll
        for (int w2 = 0; w2 < WPB; ++w2) s += bkt[w2][i];
        atomicAdd(&g_sumn[i], s);
    }
    if (t < C_) atomicAdd(&g_cnt[t], scntf[t]);

    // ---- last-block epilogue (no separate k_final launch) ----
    __threadfence();
    if (t == 0) s_last = (atomicAdd(&g_done, 1u) == GRID_ - 1u) ? 1 : 0;
    __syncthreads();
    if (!s_last) return;

    float* cs    = bkt[0];            // 19*33 floats (bucket free now)
    float* cn    = cs + C_ * 33;
    float* simA  = cn + C_;
    float* spres = simA + C_;
    float* srow  = spres + C_;

    if (t < C_) srow[t] = 0.f;
    #pragma unroll
    for (int i = 0; i < 3; ++i) {
        const int c = w + 8 * i;
        if (c < C_) {
            float count = g_cnt[c];
            float denom = fmaxf(count, 1.f);
            float ctr   = g_sumv[c * 32 + lane] / denom;
            float nsum  = g_sumn[c * 32 + lane];
            cs[c * 33 + lane] = ctr;
            g_sumv[c * 32 + lane] = 0.f;       // reset for next replay
            g_sumn[c * 32 + lane] = 0.f;

            float s = ctr * ctr;
            #pragma unroll
            for (int o = 16; o; o >>= 1) s += __shfl_xor_sync(FULL, s, o);
            float cnorm = sqrtf(s);

            float scd = nsum * ctr;            // seg_cos numerator
            #pragma unroll
            for (int o = 16; o; o >>= 1) scd += __shfl_xor_sync(FULL, scd, o);

            if (lane == 0) {
                bool pres = count > 0.f;
                float segcos = scd / fmaxf(cnorm, 1e-30f);
                cn[c]    = cnorm;
                simA[c]  = pres ? (1.f - segcos / denom) : 0.f;
                spres[c] = pres ? 1.f : 0.f;
                g_cnt[c] = 0.f;
            }
        }
    }
    if (t == 0) g_done = 0u;
    __syncthreads();

    // pairwise diff terms of the 19x19 center-cosine matrix
    for (int idx = t; idx < C_ * C_; idx += 256) {
        const int ii = idx / C_;
        const int jj = idx - ii * C_;
        float dot = 0.f;
        #pragma unroll
        for (int dd = 0; dd < D_; ++dd)
            dot = fmaf(cs[ii * 33 + dd], cs[jj * 33 + dd], dot);
        float cosv = dot / fmaxf(cn[ii] * cn[jj], EPS_);
        float term = (ii == jj) ? (1.f - cosv) : fmaxf(cosv, 0.f);
        atomicAdd(&srow[ii], term);
    }
    __syncthreads();

    if (t < 32) {
        float tot = (t < C_) ? simA[t] + spres[t] * (srow[t] / (float)C_) : 0.f;
        #pragma unroll
        for (int o = 16; o; o >>= 1) tot += __shfl_xor_sync(FULL, tot, o);
        if (t == 0) out[0] = tot;
    }
}

// ---------------- launcher --------------------------------------------------
extern "C" void kernel_launch(void* const* d_in, const int* in_sizes, int n_in,
                              void* d_out, int out_size) {
    (void)in_sizes; (void)n_in; (void)out_size;
    const float* in  = (const float*)d_in[0];
    const void*  tgt = d_in[1];
    float*       out = (float*)d_out;

    k_all<<<GRID_, 256>>>(in, tgt, out);
}

// round 16
// speedup vs baseline: 1.4613x; 1.4613x over previous
#include <cuda_runtime.h>
#include <cuda_fp16.h>

// Problem constants (fixed for this instance)
#define HW_   262144          // H*W = 512*512
#define D_    32
#define C_    19
#define N_    2097152         // B*H*W
#define TILE_ 256
#define NT_   8192            // N / TILE_
#define GRID_ 592             // 4 blocks/SM * 148
#define PITCH_H 36            // halfs per slot row (72 B, 8B-aligned)
#define EPS_  1e-8f

// ---------------- scratch (zero-initialized device globals) -----------------
// The in-kernel epilogue resets all of these, so every graph replay is clean.
__device__ float    g_sumv[C_ * D_];   // per-class sums of x
__device__ float    g_sumn[C_ * D_];   // per-class sums of x/||x||
__device__ float    g_cnt[C_];         // per-class counts
__device__ unsigned g_tile;            // dynamic work counter
__device__ unsigned g_done;            // finished-block counter

__global__ void __launch_bounds__(256, 4)
k_all(const float* __restrict__ in, const void* __restrict__ tgt,
      float* __restrict__ out) {
    __shared__ __half hbkt[TILE_ * PITCH_H];  // fp16 bucket, 18 KB
    __shared__ float  rbuf[TILE_];            // per-slot 1/||x|| (fp32)
    __shared__ int    scount[C_];
    __shared__ int    s_next;
    __shared__ int    s_is64, s_last;
    // epilogue scratch
    __shared__ float  cs[C_ * 33];
    __shared__ float  cn[C_], simA[C_], spres[C_], srow[C_];

    const int t    = threadIdx.x;
    const int w    = t >> 5;
    const int lane = t & 31;
    const unsigned FULL = 0xffffffffu;

    if (t == 0) {
        // int64 labels in [0,19): every odd 32-bit word is 0.
        const unsigned* wd = (const unsigned*)tgt;
        int is64 = 1;
        #pragma unroll
        for (int k = 0; k < 16; k++)
            if (wd[2 * k + 1] != 0u) is64 = 0;
        s_is64 = is64;
    }
    __syncthreads();
    const int is64 = s_is64;
    const long long* t64 = (const long long*)tgt;
    const int*       t32 = (const int*)tgt;

    // register accumulators: warp w owns classes w, w+8, w+16
    float sv[3] = {0.f, 0.f, 0.f};
    float sn[3] = {0.f, 0.f, 0.f};
    float cr[3] = {0.f, 0.f, 0.f};

    for (;;) {
        // fetch next tile + zero histogram
        if (t == 0) s_next = (int)atomicAdd(&g_tile, 1u);
        if (t < C_) scount[t] = 0;
        __syncthreads();                          // sync0
        const int tile = s_next;
        if (tile >= NT_) break;

        const int p  = tile * TILE_ + t;          // this thread's pixel
        const int b  = p >> 18;
        const int hw = p & (HW_ - 1);
        const float* bp = in + (size_t)b * ((size_t)D_ * HW_) + hw;

        // label first (hist depends on it), then batch the 32 feature LDGs
        int lab = is64 ? (int)t64[p] : t32[p];
        float v[D_];
        #pragma unroll
        for (int d = 0; d < D_; ++d) v[d] = bp[(size_t)d * HW_];

        // histogram + within-class rank (feature loads fly meanwhile)
        unsigned m  = __match_any_sync(FULL, lab);
        int lead    = __ffs(m) - 1;
        int rank    = __popc(m & ((1u << lane) - 1u));
        int wofs    = 0;
        if (lane == lead) wofs = atomicAdd(&scount[lab], __popc(m));
        wofs = __shfl_sync(FULL, wofs, lead);
        __syncthreads();                          // sync1

        // redundant per-warp exclusive scan of the 19 counts
        int cv = (lane < C_) ? scount[lane] : 0;
        int sc = cv;
        #pragma unroll
        for (int o = 1; o < 32; o <<= 1) {
            int nn = __shfl_up_sync(FULL, sc, o);
            if (lane >= o) sc += nn;
        }
        int mybase = __shfl_sync(FULL, sc - cv, lab);   // sbase[lab]

        // norm (v landed by now), then pack + scatter fp16 row
        float ss = 0.f;
        #pragma unroll
        for (int d = 0; d < D_; ++d) ss = fmaf(v[d], v[d], ss);
        float r = rsqrtf(fmaxf(ss, 1e-24f));      // 1/||x||

        const int slot = mybase + wofs + rank;
        uint2* q = (uint2*)&hbkt[slot * PITCH_H];
        #pragma unroll
        for (int k = 0; k < 8; ++k) {
            __half2 a = __floats2half2_rn(v[4 * k + 0], v[4 * k + 1]);
            __half2 c2 = __floats2half2_rn(v[4 * k + 2], v[4 * k + 3]);
            q[k] = make_uint2(*(unsigned*)&a, *(unsigned*)&c2);
        }
        rbuf[slot] = r;
        __syncthreads();                          // sync2

        // gather: register accumulation per owned class (lane = dim)
        #pragma unroll
        for (int i = 0; i < 3; ++i) {
            const int c = w + 8 * i;
            if (c < C_) {
                const int bs = __shfl_sync(FULL, sc - cv, c); // sbase[c]
                const int cc = __shfl_sync(FULL, cv, c);      // scount[c]
                cr[i] += (float)cc;
                float s0 = 0.f, n0 = 0.f, s1 = 0.f, n1 = 0.f;
                for (int k0 = 0; k0 < cc; k0 += 32) {
                    const int rem = min(32, cc - k0);
                    const float rl = (lane < rem) ? rbuf[bs + k0 + lane] : 0.f;
                    const __half* hb = &hbkt[(bs + k0) * PITCH_H + lane];
                    int k = 0;
                    for (; k + 1 < rem; k += 2) {
                        float a0 = __half2float(hb[k * PITCH_H]);
                        float a1 = __half2float(hb[(k + 1) * PITCH_H]);
                        float r0 = __shfl_sync(FULL, rl, k);
                        float r1 = __shfl_sync(FULL, rl, k + 1);
                        s0 += a0; n0 = fmaf(a0, r0, n0);
                        s1 += a1; n1 = fmaf(a1, r1, n1);
                    }
                    if (k < rem) {
                        float a0 = __half2float(hb[k * PITCH_H]);
                        float r0 = __shfl_sync(FULL, rl, k);
                        s0 += a0; n0 = fmaf(a0, r0, n0);
                    }
                }
                sv[i] += s0 + s1;
                sn[i] += n0 + n1;
            }
        }
        // no trailing barrier: scatter(i+1) is 2 barriers deep (sync0+sync1)
    }

    // flush per-block class totals
    #pragma unroll
    for (int i = 0; i < 3; ++i) {
        const int c = w + 8 * i;
        if (c < C_) {
            atomicAdd(&g_sumv[c * 32 + lane], sv[i]);
            atomicAdd(&g_sumn[c * 32 + lane], sn[i]);
            if (lane == 0) atomicAdd(&g_cnt[c], cr[i]);
        }
    }

    // ---- last-block epilogue (replaces a separate k_final launch) ----
    __threadfence();
    if (t == 0) s_last = (atomicAdd(&g_done, 1u) == GRID_ - 1u) ? 1 : 0;
    __syncthreads();
    if (!s_last) return;

    if (t < C_) srow[t] = 0.f;
    #pragma unroll
    for (int i = 0; i < 3; ++i) {
        const int c = w + 8 * i;
        if (c < C_) {
            float count = g_cnt[c];
            float denom = fmaxf(count, 1.f);
            float ctr   = g_sumv[c * 32 + lane] / denom;
            float nsum  = g_sumn[c * 32 + lane];
            cs[c * 33 + lane] = ctr;
            g_sumv[c * 32 + lane] = 0.f;      // reset for next replay
            g_sumn[c * 32 + lane] = 0.f;

            float s = ctr * ctr;
            #pragma unroll
            for (int o = 16; o; o >>= 1) s += __shfl_xor_sync(FULL, s, o);
            float cnorm = sqrtf(s);

            float scd = nsum * ctr;           // seg_cos numerator
            #pragma unroll
            for (int o = 16; o; o >>= 1) scd += __shfl_xor_sync(FULL, scd, o);

            if (lane == 0) {
                bool pres = count > 0.f;
                float segcos = scd / fmaxf(cnorm, 1e-30f);
                cn[c]    = cnorm;
                simA[c]  = pres ? (1.f - segcos / denom) : 0.f;
                spres[c] = pres ? 1.f : 0.f;
                g_cnt[c] = 0.f;
            }
        }
    }
    if (t == 0) { g_tile = 0u; g_done = 0u; }
    __syncthreads();

    // pairwise diff terms of the 19x19 center-cosine matrix
    for (int idx = t; idx < C_ * C_; idx += 256) {
        const int ii = idx / C_;
        const int jj = idx - ii * C_;
        float dot = 0.f;
        #pragma unroll
        for (int dd = 0; dd < D_; ++dd)
            dot = fmaf(cs[ii * 33 + dd], cs[jj * 33 + dd], dot);
        float cosv = dot / fmaxf(cn[ii] * cn[jj], EPS_);
        float term = (ii == jj) ? (1.f - cosv) : fmaxf(cosv, 0.f);
        atomicAdd(&srow[ii], term);
    }
    __syncthreads();

    if (t < 32) {
        float tot = (t < C_) ? simA[t] + spres[t] * (srow[t] / (float)C_) : 0.f;
        #pragma unroll
        for (int o = 16; o; o >>= 1) tot += __shfl_xor_sync(FULL, tot, o);
        if (t == 0) out[0] = tot;
    }
}

// ---------------- launcher --------------------------------------------------
extern "C" void kernel_launch(void* const* d_in, const int* in_sizes, int n_in,
                              void* d_out, int out_size) {
    (void)in_sizes; (void)n_in; (void)out_size;
    const float* in  = (const float*)d_in[0];
    const void*  tgt = d_in[1];
    float*       out = (float*)d_out;

    k_all<<<GRID_, 256>>>(in, tgt, out);
}